// round 1
// baseline (speedup 1.0000x reference)
#include <cuda_runtime.h>
#include <cuda_bf16.h>
#include <cstdint>

// out[v, t, n] = tlut[encoded[t, n], v]
// tlut:   (65536, 2) float32  -> each row is a contiguous float2
// encoded:(128, 262144) int32
// out:    (2, 128, 262144) float32
//
// Strategy: thread handles 4 consecutive n. int4 load of encoded,
// 4x float2 LUT gathers (L1/L2 resident, 512KB table), 2x float4
// coalesced stores (one per output plane).

static constexpr long long TB_ = 128;
static constexpr long long N_  = 262144;
static constexpr long long TOTAL  = TB_ * N_;        // 33,554,432 elements per plane
static constexpr long long TOTAL4 = TOTAL / 4;       // 8,388,608 int4/float4 quads

__global__ void __launch_bounds__(256, 8)
bitshift_lut_gather_kernel(const float2* __restrict__ lut,
                           const int4*  __restrict__ enc,
                           float4* __restrict__ out0,
                           float4* __restrict__ out1)
{
    long long i = (long long)blockIdx.x * blockDim.x + threadIdx.x;
    if (i >= TOTAL4) return;

    int4 e = enc[i];

    // four independent 8B gathers — high MLP, table is L2-resident
    float2 a = __ldg(&lut[e.x]);
    float2 b = __ldg(&lut[e.y]);
    float2 c = __ldg(&lut[e.z]);
    float2 d = __ldg(&lut[e.w]);

    out0[i] = make_float4(a.x, b.x, c.x, d.x);   // plane v=0
    out1[i] = make_float4(a.y, b.y, c.y, d.y);   // plane v=1
}

extern "C" void kernel_launch(void* const* d_in, const int* in_sizes, int n_in,
                              void* d_out, int out_size)
{
    const float2* lut = (const float2*)d_in[0];           // tlut (65536, 2)
    const int4*   enc = (const int4*)d_in[1];             // encoded (128, 262144)
    float* out = (float*)d_out;                            // (2, 128, 262144)

    float4* out0 = (float4*)out;                           // plane v=0
    float4* out1 = (float4*)(out + TOTAL);                 // plane v=1

    const int threads = 256;
    const int blocks  = (int)((TOTAL4 + threads - 1) / threads);
    bitshift_lut_gather_kernel<<<blocks, threads>>>(lut, enc, out0, out1);
}